// round 3
// baseline (speedup 1.0000x reference)
#include <cuda_runtime.h>
#include <cstdint>

// ---------------- problem constants ----------------
#define NODES   512
#define FSTRIDE 8272           // 8271 features + 1 zero pad (16B-aligned rows)
#define H1      256

// ---------------- device scratch (static, no allocation) ----------------
__device__ float g_feat[NODES * FSTRIDE];        // ~16.9 MB feature matrix
__device__ float g_np[NODES * 8 * 3];            // per (node,split): hs_sum, sum d12^2, sum d23^2
__device__ float g_spec[NODES];                  // spectral entropy per node
__device__ float g_gpart[8 * NODES * H1];        // split-K GEMM partials
__device__ float g_h1[NODES * H1];               // relu(feat@W1+b1)
struct Misc { float h_temporal; float kembed[64]; };
__device__ Misc g_misc;

__device__ __constant__ float c_cos16[16] = {
  1.0f, 0.9238795325112867f, 0.7071067811865476f, 0.3826834323650898f,
  0.0f,-0.3826834323650898f,-0.7071067811865476f,-0.9238795325112867f,
 -1.0f,-0.9238795325112867f,-0.7071067811865476f,-0.3826834323650898f,
  0.0f, 0.3826834323650898f, 0.7071067811865476f, 0.9238795325112867f };
__device__ __constant__ float c_sin16[16] = {
  0.0f, 0.3826834323650898f, 0.7071067811865476f, 0.9238795325112867f,
  1.0f, 0.9238795325112867f, 0.7071067811865476f, 0.3826834323650898f,
  0.0f,-0.3826834323650898f,-0.7071067811865476f,-0.9238795325112867f,
 -1.0f,-0.9238795325112867f,-0.7071067811865476f,-0.3826834323650898f };

// ---------------- threefry-2x32-20 (JAX schedule), partitionable draw ----------------
struct TFK { unsigned a0,a1,a2, b0,b1,b2, c0,c1,c2, d0,d1,d2; };

__device__ __forceinline__ unsigned tfb(unsigned k0, unsigned k1, unsigned ks2, unsigned idx)
{
  unsigned x0 = k0;          // x0_in = 0 (hi word of iota) + k0
  unsigned x1 = idx + k1;    // x1_in = flat index (lo word) + k1
#define TFR(r) { x0 += x1; x1 = __funnelshift_l(x1, x1, (r)); x1 ^= x0; }
  TFR(13) TFR(15) TFR(26) TFR(6)   x0 += k1;  x1 += ks2 + 1u;
  TFR(17) TFR(29) TFR(16) TFR(24)  x0 += ks2; x1 += k0  + 2u;
  TFR(13) TFR(15) TFR(26) TFR(6)   x0 += k0;  x1 += k1  + 3u;
  TFR(17) TFR(29) TFR(16) TFR(24)  x0 += k1;  x1 += ks2 + 4u;
  TFR(13) TFR(15) TFR(26) TFR(6)   x0 += ks2; x1 += k0  + 5u;
#undef TFR
  return x0 ^ x1;  // partitionable 32-bit fold
}

// JAX normal() from raw 32 bits: uniform(-0.99999994, 1) then sqrt(2)*erfinv (XLA/Giles poly)
__device__ __forceinline__ float nrm(unsigned bits)
{
  float u = __uint_as_float((bits >> 9) | 0x3F800000u) - 1.0f;  // [0,1)
  float x = fmaf(u, 2.0f, -0.99999994f);   // span (hi-lo) rounds to exactly 2.0f
  x = fmaxf(x, -0.99999994f);
  float w = -__logf(fmaf(x, -x, 1.0f));
  float p;
  if (w < 5.0f) {
    w -= 2.5f;
    p = 2.81022636e-08f;
    p = fmaf(p, w, 3.43273939e-07f);
    p = fmaf(p, w, -3.5233877e-06f);
    p = fmaf(p, w, -4.39150654e-06f);
    p = fmaf(p, w, 0.00021858087f);
    p = fmaf(p, w, -0.00125372503f);
    p = fmaf(p, w, -0.00417768164f);
    p = fmaf(p, w, 0.246640727f);
    p = fmaf(p, w, 1.50140941f);
  } else {
    w = sqrtf(w) - 3.0f;
    p = -0.000200214257f;
    p = fmaf(p, w, 0.000100950558f);
    p = fmaf(p, w, 0.00134934322f);
    p = fmaf(p, w, -0.00367342844f);
    p = fmaf(p, w, 0.00573950773f);
    p = fmaf(p, w, -0.0076224613f);
    p = fmaf(p, w, 0.00943887047f);
    p = fmaf(p, w, 1.00167406f);
    p = fmaf(p, w, 2.83297682f);
  }
  return 1.41421356f * (p * x);
}

// ---------------- block reductions (256 threads) ----------------
__device__ __forceinline__ float bsum256(float v, float* red)
{
  #pragma unroll
  for (int o = 16; o; o >>= 1) v += __shfl_down_sync(0xffffffffu, v, o);
  if ((threadIdx.x & 31) == 0) red[threadIdx.x >> 5] = v;
  __syncthreads();
  if (threadIdx.x == 0) { float r = red[0];
    #pragma unroll
    for (int i = 1; i < 8; i++) r += red[i];
    red[0] = r; }
  __syncthreads();
  float r = red[0];
  __syncthreads();
  return r;
}
__device__ __forceinline__ float bmin256(float v, float* red)
{
  #pragma unroll
  for (int o = 16; o; o >>= 1) v = fminf(v, __shfl_down_sync(0xffffffffu, v, o));
  if ((threadIdx.x & 31) == 0) red[threadIdx.x >> 5] = v;
  __syncthreads();
  if (threadIdx.x == 0) { float r = red[0];
    #pragma unroll
    for (int i = 1; i < 8; i++) r = fminf(r, red[i]);
    red[0] = r; }
  __syncthreads();
  float r = red[0];
  __syncthreads();
  return r;
}
__device__ __forceinline__ float bmax256(float v, float* red)
{
  #pragma unroll
  for (int o = 16; o; o >>= 1) v = fmaxf(v, __shfl_down_sync(0xffffffffu, v, o));
  if ((threadIdx.x & 31) == 0) red[threadIdx.x >> 5] = v;
  __syncthreads();
  if (threadIdx.x == 0) { float r = red[0];
    #pragma unroll
    for (int i = 1; i < 8; i++) r = fmaxf(r, red[i]);
    red[0] = r; }
  __syncthreads();
  float r = red[0];
  __syncthreads();
  return r;
}

// ---------------- K0: h_temporal + k_embed ----------------
__global__ void __launch_bounds__(256) k_misc(const float* __restrict__ eh,
                                              const int* __restrict__ kptr)
{
  __shared__ float red[8];
  int tid = threadIdx.x;
  float s = 0.f;
  for (int i = tid; i < 1536; i += 256) s += eh[i + 512] - eh[i];
  float tot = bsum256(s, red);
  float mean = tot / 1536.0f;
  float v = 0.f;
  for (int i = tid; i < 1536; i += 256) {
    float d = (eh[i + 512] - eh[i]) - mean;
    v = fmaf(d, d, v);
  }
  float VAR = bsum256(v, red) / 1535.0f;
  if (tid == 0)
    g_misc.h_temporal = 0.5f * logf(17.07946844534713f * (VAR + 1e-6f));
  if (tid < 32) {
    float kf = (float)(*kptr);
    float c  = -0.29710775393471563f;   // -ln(10000)/31 in f32
    float e  = expf((float)tid * c);
    float val = kf * e;
    g_misc.kembed[tid]      = sinf(val);
    g_misc.kembed[tid + 32] = cosf(val);
  }
}

// ---------------- K1: RNG-heavy entropies (h_score numerator, d12^2, d23^2) ----------------
__global__ void __launch_bounds__(256) k_rng(const float* __restrict__ z,
                                             const int* __restrict__ ti,
                                             const int* __restrict__ fi, TFK K)
{
  __shared__ float red[8];
  int node = blockIdx.x >> 3, split = blockIdx.x & 7;
  int t = ti[node], f = fi[node];
  int tid = threadIdx.x;
  float hs = 0.f, s12 = 0.f, s23 = 0.f;
  #pragma unroll 1
  for (int q = 0; q < 4; q++) {
    int p = split * 1024 + q * 256 + tid;
    int b = p >> 8, i = (p >> 4) & 15, j = p & 15;
    float zv = z[((size_t)(b * 4096 + t * 16 + i)) * 512 + f * 16 + j];
    unsigned mb = (unsigned)node * 81920u + (unsigned)p;
    float m[10];
    #pragma unroll
    for (int s = 0; s < 10; s++)
      m[s] = zv + 0.1f * nrm(tfb(K.a0, K.a1, K.a2, mb + (unsigned)s * 8192u));
    float sm = 0.f;
    #pragma unroll
    for (int s = 0; s < 10; s++) sm += m[s];
    float mean = sm / 10.0f;
    float v = 0.f;
    #pragma unroll
    for (int s = 0; s < 10; s++) { float d = m[s] - mean; v = fmaf(d, d, v); }
    v = v / 9.0f;
    hs += 0.5f * logf(17.07946844534713f * (v + 1e-8f));
    unsigned pb = (unsigned)node * 8192u + (unsigned)p;
    float e1 = 0.1f  * nrm(tfb(K.b0, K.b1, K.b2, pb));
    float e2 = 0.05f * nrm(tfb(K.c0, K.c1, K.c2, pb));
    float e3 = 0.02f * nrm(tfb(K.d0, K.d1, K.d2, pb));
    float d1 = (zv + e1) - (zv + e2);
    float d2 = (zv + e2) - (zv + e3);
    s12 = fmaf(d1, d1, s12);
    s23 = fmaf(d2, d2, s23);
  }
  hs  = bsum256(hs, red);
  s12 = bsum256(s12, red);
  s23 = bsum256(s23, red);
  if (tid == 0) {
    float* o = &g_np[(node * 8 + split) * 3];
    o[0] = hs; o[1] = s12; o[2] = s23;
  }
}

// ---------------- K2: per-node stats, median, spectral entropy, feature assembly ----------------
__global__ void __launch_bounds__(256) k_node(const float* __restrict__ z,
                                              const int* __restrict__ ti,
                                              const int* __restrict__ fi)
{
  __shared__ float sz[8192];
  __shared__ float red[8];
  int node = blockIdx.x, tid = threadIdx.x;
  int t = ti[node], f = fi[node];
  float* fb = &g_feat[(size_t)node * FSTRIDE];

  for (int p = tid; p < 8192; p += 256) {
    int b = p >> 8, i = (p >> 4) & 15, j = p & 15;
    float v = z[((size_t)(b * 4096 + t * 16 + i)) * 512 + f * 16 + j];
    sz[p] = v;
    fb[p] = v;
  }
  __syncthreads();

  // stats pass 1
  float s = 0.f, sa = 0.f, sq = 0.f, cp = 0.f, cn = 0.f, mn = 3e38f, mx = -3e38f;
  for (int p = tid; p < 8192; p += 256) {
    float v = sz[p];
    s += v; sa += fabsf(v); sq = fmaf(v, v, sq);
    if (v > 0.f) cp += 1.f;
    if (v < 0.f) cn += 1.f;
    mn = fminf(mn, v); mx = fmaxf(mx, v);
  }
  float S  = bsum256(s,  red);
  float SA = bsum256(sa, red);
  float SQ = bsum256(sq, red);
  float CP = bsum256(cp, red);
  float CN = bsum256(cn, red);
  float MN = bmin256(mn, red);
  float MX = bmax256(mx, red);
  float mean = S / 8192.0f;

  float cv = 0.f;
  for (int p = tid; p < 8192; p += 256) { float d = sz[p] - mean; cv = fmaf(d, d, cv); }
  float VAR = bsum256(cv, red) / 8191.0f;

  // exact median (lower-middle of sorted, rank 4095) via bit bisection on order-mapped keys
  unsigned lo = 0u, hi = 0xFFFFFFFFu;
  #pragma unroll 1
  for (int it = 0; it < 32 && lo < hi; it++) {
    unsigned mid = lo + ((hi - lo) >> 1);
    float c = 0.f;
    for (int p = tid; p < 8192; p += 256) {
      unsigned u = __float_as_uint(sz[p]);
      unsigned kk = (u & 0x80000000u) ? ~u : (u | 0x80000000u);
      if (kk <= mid) c += 1.f;
    }
    float C = bsum256(c, red);
    if (C >= 4096.f) hi = mid; else lo = mid + 1u;
  }
  float med;
  { unsigned kk = lo;
    unsigned u = (kk >> 31) ? (kk ^ 0x80000000u) : ~kk;
    med = __uint_as_float(u); }

  // spectral entropy: 16-pt DFT along local time axis, per (b, col)
  float hsp = 0.f;
  for (int c = tid; c < 512; c += 256) {
    int b = c >> 4, j = c & 15;
    float xr[16];
    #pragma unroll
    for (int i2 = 0; i2 < 16; i2++) xr[i2] = sz[b * 256 + i2 * 16 + j];
    float ps[9];
    #pragma unroll
    for (int k2 = 0; k2 < 9; k2++) {
      float re = 0.f, im = 0.f;
      #pragma unroll
      for (int i2 = 0; i2 < 16; i2++) {
        int w = (k2 * i2) & 15;
        re = fmaf(xr[i2], c_cos16[w], re);
        im = fmaf(xr[i2], c_sin16[w], im);
      }
      ps[k2] = fmaf(re, re, im * im);
    }
    float den = ps[0] + ps[8];
    #pragma unroll
    for (int k2 = 1; k2 < 8; k2++) den += 2.0f * ps[k2];
    float dent = den + 1e-8f;
    #pragma unroll
    for (int k2 = 0; k2 < 9; k2++) {
      float pn = ps[k2] / dent;
      float tm = pn * logf(pn + 1e-8f);
      hsp += (k2 == 0 || k2 == 8) ? tm : 2.0f * tm;
    }
  }
  float HS = bsum256(hsp, red);
  if (tid == 0) g_spec[node] = -HS;

  // feature tail
  if (tid < 64) fb[8192 + tid] = g_misc.kembed[tid];
  if (tid == 64) {
    float tf = (float)t, ff = (float)f;
    fb[8256] = sinf(0.1f * tf); fb[8257] = cosf(0.1f * tf);
    fb[8258] = sinf(0.1f * ff); fb[8259] = cosf(0.1f * ff);
    fb[8260] = 0.5f;   // S_SCALE / MAX_SCALES
  }
  if (tid == 0) {
    fb[8261] = mean;
    fb[8262] = sqrtf(VAR);
    fb[8263] = MN;
    fb[8264] = MX;
    fb[8265] = med;
    fb[8266] = VAR;
    fb[8267] = sqrtf(SQ);
    fb[8268] = SA;
    fb[8269] = CP;
    fb[8270] = CN;
    fb[8271] = 0.f;    // pad
  }
}

// ---------------- K4: GEMM1 feat(512x8271) @ W1(8271x256), split-K=8 ----------------
__global__ void __launch_bounds__(256) k_gemm1(const float* __restrict__ W1)
{
  __shared__ float As[16][64];
  __shared__ float Bs[16][64];
  int mt = blockIdx.x * 64, nt = blockIdx.y * 64, kz = blockIdx.z;
  int kb = kz * 1040;
  int iters = (kz == 7) ? 62 : 65;
  int t = threadIdx.x, tx = t & 15, ty = t >> 4;
  float acc[4][4];
  #pragma unroll
  for (int i = 0; i < 4; i++)
    #pragma unroll
    for (int j = 0; j < 4; j++) acc[i][j] = 0.f;
  int am = t & 63, ak = (t >> 6) * 4;
  int bk0 = t >> 4, bn = (t & 15) * 4;

  for (int it = 0; it < iters; it++) {
    int k0 = kb + it * 16;
    float4 av = *(const float4*)&g_feat[(size_t)(mt + am) * FSTRIDE + k0 + ak];
    int gk = k0 + bk0;
    float4 bv = make_float4(0.f, 0.f, 0.f, 0.f);
    if (gk < 8271) bv = *(const float4*)&W1[(size_t)gk * 256 + nt + bn];
    __syncthreads();
    As[ak + 0][am] = av.x; As[ak + 1][am] = av.y;
    As[ak + 2][am] = av.z; As[ak + 3][am] = av.w;
    *(float4*)&Bs[bk0][bn] = bv;
    __syncthreads();
    #pragma unroll
    for (int kk = 0; kk < 16; kk++) {
      float4 a  = *(const float4*)&As[kk][ty * 4];
      float4 bq = *(const float4*)&Bs[kk][tx * 4];
      float ar[4] = {a.x, a.y, a.z, a.w};
      float br[4] = {bq.x, bq.y, bq.z, bq.w};
      #pragma unroll
      for (int i = 0; i < 4; i++)
        #pragma unroll
        for (int j = 0; j < 4; j++)
          acc[i][j] = fmaf(ar[i], br[j], acc[i][j]);
    }
  }
  float* op = &g_gpart[(size_t)kz * (NODES * H1)];
  #pragma unroll
  for (int i = 0; i < 4; i++) {
    float4 vv = make_float4(acc[i][0], acc[i][1], acc[i][2], acc[i][3]);
    *(float4*)&op[(size_t)(mt + ty * 4 + i) * 256 + nt + tx * 4] = vv;
  }
}

// ---------------- K5: reduce split-K partials + bias + relu ----------------
__global__ void __launch_bounds__(256) k_bias1(const float* __restrict__ b1)
{
  int m = blockIdx.x, n = threadIdx.x;
  float a = 0.f;
  #pragma unroll
  for (int kz = 0; kz < 8; kz++)
    a += g_gpart[(size_t)kz * (NODES * H1) + m * 256 + n];
  a += b1[n];
  g_h1[m * 256 + n] = fmaxf(a, 0.f);
}

// ---------------- K6: MLP tail + softmax + combine ----------------
__global__ void __launch_bounds__(128) k_tail(const float* __restrict__ W2, const float* __restrict__ b2,
                                              const float* __restrict__ W3, const float* __restrict__ b3,
                                              const float* __restrict__ W4, const float* __restrict__ b4,
                                              float* __restrict__ out)
{
  __shared__ float h1s[256], h2s[128], h3s[64], lg[5];
  int node = blockIdx.x, tid = threadIdx.x;
  h1s[tid]       = g_h1[node * 256 + tid];
  h1s[tid + 128] = g_h1[node * 256 + tid + 128];
  __syncthreads();
  { float a = b2[tid];
    #pragma unroll 8
    for (int k = 0; k < 256; k++) a = fmaf(h1s[k], W2[k * 128 + tid], a);
    h2s[tid] = fmaxf(a, 0.f); }
  __syncthreads();
  if (tid < 64) {
    float a = b3[tid];
    #pragma unroll 8
    for (int k = 0; k < 128; k++) a = fmaf(h2s[k], W3[k * 64 + tid], a);
    h3s[tid] = fmaxf(a, 0.f);
  }
  __syncthreads();
  if (tid < 5) {
    float a = b4[tid];
    #pragma unroll 8
    for (int k = 0; k < 64; k++) a = fmaf(h3s[k], W4[k * 5 + tid], a);
    lg[tid] = a;
  }
  __syncthreads();
  if (tid == 0) {
    float hs = 0.f, s12 = 0.f, s23 = 0.f;
    #pragma unroll
    for (int sp = 0; sp < 8; sp++) {
      const float* q = &g_np[(node * 8 + sp) * 3];
      hs += q[0]; s12 += q[1]; s23 += q[2];
    }
    float h_score = hs / 8192.0f;
    float kl1 = logf(0.05f / 0.1f)
              + (0.1f * 0.1f + s12 / 8192.0f) / (2.0f * (0.05f * 0.05f)) - 0.5f;
    float kl2 = logf(0.02f / 0.05f)
              + (0.05f * 0.05f + s23 / 8192.0f) / (2.0f * (0.02f * 0.02f)) - 0.5f;
    float comps[5] = { h_score, -logf(1e-8f), kl1 + kl2, g_misc.h_temporal, g_spec[node] };
    float mxv = lg[0];
    #pragma unroll
    for (int i = 1; i < 5; i++) mxv = fmaxf(mxv, lg[i]);
    float e[5], se = 0.f;
    #pragma unroll
    for (int i = 0; i < 5; i++) { e[i] = expf(lg[i] - mxv); se += e[i]; }
    float o = 0.f;
    #pragma unroll
    for (int i = 0; i < 5; i++) o += (e[i] / se) * comps[i];
    out[node] = o;
  }
}

// ---------------- host: threefry for the 4 subkeys of key(42) ----------------
static void tf20_host(unsigned k0, unsigned k1, unsigned x0, unsigned x1,
                      unsigned* o0, unsigned* o1)
{
  unsigned ks2 = k0 ^ k1 ^ 0x1BD11BDAu;
  unsigned a = x0 + k0, b = x1 + k1;
#define RR(r) { a += b; b = (b << (r)) | (b >> (32 - (r))); b ^= a; }
  RR(13) RR(15) RR(26) RR(6)   a += k1;  b += ks2 + 1u;
  RR(17) RR(29) RR(16) RR(24)  a += ks2; b += k0  + 2u;
  RR(13) RR(15) RR(26) RR(6)   a += k0;  b += k1  + 3u;
  RR(17) RR(29) RR(16) RR(24)  a += k1;  b += ks2 + 4u;
  RR(13) RR(15) RR(26) RR(6)   a += ks2; b += k0  + 5u;
#undef RR
  *o0 = a; *o1 = b;
}

extern "C" void kernel_launch(void* const* d_in, const int* in_sizes, int n_in,
                              void* d_out, int out_size)
{
  const float* z   = (const float*)d_in[0];
  // d_in[1] = y_obs: mathematically unused (h_guid reduces to -log(1e-8))
  const float* eh  = (const float*)d_in[2];
  const float* W1  = (const float*)d_in[3];
  const float* b1  = (const float*)d_in[4];
  const float* W2  = (const float*)d_in[5];
  const float* b2  = (const float*)d_in[6];
  const float* W3  = (const float*)d_in[7];
  const float* b3  = (const float*)d_in[8];
  const float* W4  = (const float*)d_in[9];
  const float* b4  = (const float*)d_in[10];
  const int* t_idx = (const int*)d_in[11];
  const int* f_idx = (const int*)d_in[12];
  const int* kptr  = (const int*)d_in[13];
  float* out = (float*)d_out;

  // subkeys of jax.random.split(jax.random.key(42), 4), partitionable fold-like split
  TFK K;
  unsigned s0, s1;
  tf20_host(0u, 42u, 0u, 0u, &s0, &s1); K.a0 = s0; K.a1 = s1; K.a2 = s0 ^ s1 ^ 0x1BD11BDAu;
  tf20_host(0u, 42u, 0u, 1u, &s0, &s1); K.b0 = s0; K.b1 = s1; K.b2 = s0 ^ s1 ^ 0x1BD11BDAu;
  tf20_host(0u, 42u, 0u, 2u, &s0, &s1); K.c0 = s0; K.c1 = s1; K.c2 = s0 ^ s1 ^ 0x1BD11BDAu;
  tf20_host(0u, 42u, 0u, 3u, &s0, &s1); K.d0 = s0; K.d1 = s1; K.d2 = s0 ^ s1 ^ 0x1BD11BDAu;

  k_misc <<<1, 256>>>(eh, kptr);
  k_rng  <<<NODES * 8, 256>>>(z, t_idx, f_idx, K);
  k_node <<<NODES, 256>>>(z, t_idx, f_idx);
  k_gemm1<<<dim3(8, 4, 8), 256>>>(W1);
  k_bias1<<<NODES, 256>>>(b1);
  k_tail <<<NODES, 128>>>(W2, b2, W3, b3, W4, b4, out);
}

// round 6
// speedup vs baseline: 1.0279x; 1.0279x over previous
#include <cuda_runtime.h>
#include <cstdint>

// ---------------- problem constants ----------------
#define NODES   512
#define FSTRIDE 8288           // 8271 features + 17 zero pad (multiple of 16)
#define H1      256
#define KSPLIT  32
#define KBTOT   518            // FSTRIDE/16 k-blocks
#define KBPER   17             // ceil(518/32)

// ---------------- device scratch (static, no allocation) ----------------
__device__ float g_feat[NODES * FSTRIDE];          // ~17 MB feature matrix (zero-padded)
__device__ float g_np[NODES * 8 * 3];              // per (node,split): hs_sum, sum d12^2, sum d23^2
__device__ float g_spec[NODES];                    // spectral entropy per node
__device__ float g_gpart[KSPLIT * NODES * H1];     // split-K GEMM partials (16.8 MB)
__device__ float g_htemp[1];                       // h_temporal

__device__ __constant__ float c_cos16[16] = {
  1.0f, 0.9238795325112867f, 0.7071067811865476f, 0.3826834323650898f,
  0.0f,-0.3826834323650898f,-0.7071067811865476f,-0.9238795325112867f,
 -1.0f,-0.9238795325112867f,-0.7071067811865476f,-0.3826834323650898f,
  0.0f, 0.3826834323650898f, 0.7071067811865476f, 0.9238795325112867f };
__device__ __constant__ float c_sin16[16] = {
  0.0f, 0.3826834323650898f, 0.7071067811865476f, 0.9238795325112867f,
  1.0f, 0.9238795325112867f, 0.7071067811865476f, 0.3826834323650898f,
  0.0f,-0.3826834323650898f,-0.7071067811865476f,-0.9238795325112867f,
 -1.0f,-0.9238795325112867f,-0.7071067811865476f,-0.3826834323650898f };

// ---------------- threefry-2x32-20 (JAX schedule), partitionable draw ----------------
struct TFK { unsigned a0,a1,a2, b0,b1,b2, c0,c1,c2, d0,d1,d2; };

__device__ __forceinline__ unsigned tfb(unsigned k0, unsigned k1, unsigned ks2, unsigned idx)
{
  unsigned x0 = k0;          // x0_in = 0 (hi word of iota) + k0
  unsigned x1 = idx + k1;    // x1_in = flat index (lo word) + k1
#define TFR(r) { x0 += x1; x1 = __funnelshift_l(x1, x1, (r)); x1 ^= x0; }
  TFR(13) TFR(15) TFR(26) TFR(6)   x0 += k1;  x1 += ks2 + 1u;
  TFR(17) TFR(29) TFR(16) TFR(24)  x0 += ks2; x1 += k0  + 2u;
  TFR(13) TFR(15) TFR(26) TFR(6)   x0 += k0;  x1 += k1  + 3u;
  TFR(17) TFR(29) TFR(16) TFR(24)  x0 += k1;  x1 += ks2 + 4u;
  TFR(13) TFR(15) TFR(26) TFR(6)   x0 += ks2; x1 += k0  + 5u;
#undef TFR
  return x0 ^ x1;  // partitionable 32-bit fold
}

// JAX normal() from raw 32 bits: uniform(-0.99999994, 1) then sqrt(2)*erfinv (XLA/Giles poly)
__device__ __forceinline__ float nrm(unsigned bits)
{
  float u = __uint_as_float((bits >> 9) | 0x3F800000u) - 1.0f;  // [0,1)
  float x = fmaf(u, 2.0f, -0.99999994f);
  x = fmaxf(x, -0.99999994f);
  float w = -__logf(fmaf(x, -x, 1.0f));
  float p;
  if (w < 5.0f) {
    w -= 2.5f;
    p = 2.81022636e-08f;
    p = fmaf(p, w, 3.43273939e-07f);
    p = fmaf(p, w, -3.5233877e-06f);
    p = fmaf(p, w, -4.39150654e-06f);
    p = fmaf(p, w, 0.00021858087f);
    p = fmaf(p, w, -0.00125372503f);
    p = fmaf(p, w, -0.00417768164f);
    p = fmaf(p, w, 0.246640727f);
    p = fmaf(p, w, 1.50140941f);
  } else {
    w = sqrtf(w) - 3.0f;
    p = -0.000200214257f;
    p = fmaf(p, w, 0.000100950558f);
    p = fmaf(p, w, 0.00134934322f);
    p = fmaf(p, w, -0.00367342844f);
    p = fmaf(p, w, 0.00573950773f);
    p = fmaf(p, w, -0.0076224613f);
    p = fmaf(p, w, 0.00943887047f);
    p = fmaf(p, w, 1.00167406f);
    p = fmaf(p, w, 2.83297682f);
  }
  return 1.41421356f * (p * x);
}

// ---------------- block reductions (256 threads) ----------------
__device__ __forceinline__ float bsum256(float v, float* red)
{
  #pragma unroll
  for (int o = 16; o; o >>= 1) v += __shfl_down_sync(0xffffffffu, v, o);
  if ((threadIdx.x & 31) == 0) red[threadIdx.x >> 5] = v;
  __syncthreads();
  if (threadIdx.x == 0) { float r = red[0];
    #pragma unroll
    for (int i = 1; i < 8; i++) r += red[i];
    red[0] = r; }
  __syncthreads();
  float r = red[0];
  __syncthreads();
  return r;
}
__device__ __forceinline__ float bmin256(float v, float* red)
{
  #pragma unroll
  for (int o = 16; o; o >>= 1) v = fminf(v, __shfl_down_sync(0xffffffffu, v, o));
  if ((threadIdx.x & 31) == 0) red[threadIdx.x >> 5] = v;
  __syncthreads();
  if (threadIdx.x == 0) { float r = red[0];
    #pragma unroll
    for (int i = 1; i < 8; i++) r = fminf(r, red[i]);
    red[0] = r; }
  __syncthreads();
  float r = red[0];
  __syncthreads();
  return r;
}
__device__ __forceinline__ float bmax256(float v, float* red)
{
  #pragma unroll
  for (int o = 16; o; o >>= 1) v = fmaxf(v, __shfl_down_sync(0xffffffffu, v, o));
  if ((threadIdx.x & 31) == 0) red[threadIdx.x >> 5] = v;
  __syncthreads();
  if (threadIdx.x == 0) { float r = red[0];
    #pragma unroll
    for (int i = 1; i < 8; i++) r = fmaxf(r, red[i]);
    red[0] = r; }
  __syncthreads();
  float r = red[0];
  __syncthreads();
  return r;
}

// ---------------- K_pre: heterogeneous blocks ----------------
// blocks [0, 4096):    RNG entropies (node = bid>>3, split = bid&7)  -- long pole
// blocks [4096, 4608): per-node stats/median/spectral/feature assembly
// block  4608:         h_temporal
__global__ void __launch_bounds__(256) k_pre(const float* __restrict__ z,
                                             const float* __restrict__ eh,
                                             const int* __restrict__ kptr,
                                             const int* __restrict__ ti,
                                             const int* __restrict__ fi, TFK K)
{
  __shared__ float sz[8192];
  __shared__ float red[8];
  int bid = blockIdx.x;
  int tid = threadIdx.x;

  if (bid < 4096) {
    // ----- RNG path: pure compute, no memory traffic -----
    int node = bid >> 3, split = bid & 7;
    float hs = 0.f, s12 = 0.f, s23 = 0.f;
    #pragma unroll 1
    for (int q = 0; q < 4; q++) {
      int p = split * 1024 + q * 256 + tid;
      // h_score: var over 10 MC samples of (zl + 0.1 n); zl cancels in the variance
      unsigned mb = (unsigned)node * 81920u + (unsigned)p;
      float s1 = 0.f, s2 = 0.f;
      #pragma unroll
      for (int s = 0; s < 10; s++) {
        float n = nrm(tfb(K.a0, K.a1, K.a2, mb + (unsigned)s * 8192u));
        s1 += n;
        s2 = fmaf(n, n, s2);
      }
      float v = 0.01f * ((s2 - s1 * s1 * 0.1f) * (1.0f / 9.0f));
      hs += 0.5f * __logf(17.07946844534713f * (v + 1e-8f));  // fast log: |err| ~1e-7 abs
      // h_solver: (e1-e2)^2 and (e2-e3)^2 sums (zl cancels in the differences)
      unsigned pb = (unsigned)node * 8192u + (unsigned)p;
      float nb = nrm(tfb(K.b0, K.b1, K.b2, pb));
      float nc = nrm(tfb(K.c0, K.c1, K.c2, pb));
      float nd = nrm(tfb(K.d0, K.d1, K.d2, pb));
      float d1 = 0.1f  * nb - 0.05f * nc;
      float d2 = 0.05f * nc - 0.02f * nd;
      s12 = fmaf(d1, d1, s12);
      s23 = fmaf(d2, d2, s23);
    }
    hs  = bsum256(hs, red);
    s12 = bsum256(s12, red);
    s23 = bsum256(s23, red);
    if (tid == 0) {
      float* o = &g_np[(node * 8 + split) * 3];
      o[0] = hs; o[1] = s12; o[2] = s23;
    }
    return;
  }

  if (bid == 4608) {
    // ----- h_temporal -----
    float s = 0.f;
    for (int i = tid; i < 1536; i += 256) s += eh[i + 512] - eh[i];
    float tot = bsum256(s, red);
    float mean = tot / 1536.0f;
    float v = 0.f;
    for (int i = tid; i < 1536; i += 256) {
      float d = (eh[i + 512] - eh[i]) - mean;
      v = fmaf(d, d, v);
    }
    float VAR = bsum256(v, red) / 1535.0f;
    if (tid == 0)
      g_htemp[0] = 0.5f * logf(17.07946844534713f * (VAR + 1e-6f));
    return;
  }

  // ----- per-node path -----
  int node = bid - 4096;
  int t = ti[node], f = fi[node];
  float* fb = &g_feat[(size_t)node * FSTRIDE];

  for (int p = tid; p < 8192; p += 256) {
    int b = p >> 8, i = (p >> 4) & 15, j = p & 15;
    float v = z[((size_t)(b * 4096 + t * 16 + i)) * 512 + f * 16 + j];
    sz[p] = v;
    fb[p] = v;
  }
  __syncthreads();

  // stats pass 1
  float s = 0.f, sa = 0.f, sq = 0.f, cp = 0.f, cn = 0.f, mn = 3e38f, mx = -3e38f;
  for (int p = tid; p < 8192; p += 256) {
    float v = sz[p];
    s += v; sa += fabsf(v); sq = fmaf(v, v, sq);
    if (v > 0.f) cp += 1.f;
    if (v < 0.f) cn += 1.f;
    mn = fminf(mn, v); mx = fmaxf(mx, v);
  }
  float S  = bsum256(s,  red);
  float SA = bsum256(sa, red);
  float SQ = bsum256(sq, red);
  float CP = bsum256(cp, red);
  float CN = bsum256(cn, red);
  float MN = bmin256(mn, red);
  float MX = bmax256(mx, red);
  float mean = S / 8192.0f;

  float cv = 0.f;
  for (int p = tid; p < 8192; p += 256) { float d = sz[p] - mean; cv = fmaf(d, d, cv); }
  float VAR = bsum256(cv, red) / 8191.0f;

  // exact median (rank 4095) via bit bisection on order-mapped keys
  unsigned lo = 0u, hi = 0xFFFFFFFFu;
  #pragma unroll 1
  for (int it = 0; it < 32 && lo < hi; it++) {
    unsigned mid = lo + ((hi - lo) >> 1);
    float c = 0.f;
    for (int p = tid; p < 8192; p += 256) {
      unsigned u = __float_as_uint(sz[p]);
      unsigned kk = (u & 0x80000000u) ? ~u : (u | 0x80000000u);
      if (kk <= mid) c += 1.f;
    }
    float C = bsum256(c, red);
    if (C >= 4096.f) hi = mid; else lo = mid + 1u;
  }
  float med;
  { unsigned kk = lo;
    unsigned u = (kk >> 31) ? (kk ^ 0x80000000u) : ~kk;
    med = __uint_as_float(u); }

  // spectral entropy: 16-pt DFT along local time axis, per (b, col)
  float hsp = 0.f;
  for (int c = tid; c < 512; c += 256) {
    int b = c >> 4, j = c & 15;
    float xr[16];
    #pragma unroll
    for (int i2 = 0; i2 < 16; i2++) xr[i2] = sz[b * 256 + i2 * 16 + j];
    float ps[9];
    #pragma unroll
    for (int k2 = 0; k2 < 9; k2++) {
      float re = 0.f, im = 0.f;
      #pragma unroll
      for (int i2 = 0; i2 < 16; i2++) {
        int w = (k2 * i2) & 15;
        re = fmaf(xr[i2], c_cos16[w], re);
        im = fmaf(xr[i2], c_sin16[w], im);
      }
      ps[k2] = fmaf(re, re, im * im);
    }
    float den = ps[0] + ps[8];
    #pragma unroll
    for (int k2 = 1; k2 < 8; k2++) den += 2.0f * ps[k2];
    float dent = den + 1e-8f;
    #pragma unroll
    for (int k2 = 0; k2 < 9; k2++) {
      float pn = ps[k2] / dent;
      float tm = pn * logf(pn + 1e-8f);
      hsp += (k2 == 0 || k2 == 8) ? tm : 2.0f * tm;
    }
  }
  float HS = bsum256(hsp, red);
  if (tid == 0) g_spec[node] = -HS;

  // feature tail: k_embed computed per-block (no cross-block dependency)
  if (tid < 32) {
    float kf = (float)(*kptr);
    float val = kf * expf((float)tid * -0.29710775393471563f);  // -ln(10000)/31
    fb[8192 + tid] = sinf(val);
    fb[8224 + tid] = cosf(val);
  }
  if (tid == 64) {
    float tf = (float)t, ff = (float)f;
    fb[8256] = sinf(0.1f * tf); fb[8257] = cosf(0.1f * tf);
    fb[8258] = sinf(0.1f * ff); fb[8259] = cosf(0.1f * ff);
    fb[8260] = 0.5f;   // S_SCALE / MAX_SCALES
  }
  if (tid == 0) {
    fb[8261] = mean;
    fb[8262] = sqrtf(VAR);
    fb[8263] = MN;
    fb[8264] = MX;
    fb[8265] = med;
    fb[8266] = VAR;
    fb[8267] = sqrtf(SQ);
    fb[8268] = SA;
    fb[8269] = CP;
    fb[8270] = CN;
  }
  if (tid >= 96 && tid < 96 + 17) fb[8271 - 96 + tid] = 0.f;  // zero pad [8271, 8288)
}

// ---------------- GEMM1: feat(512x8288) @ W1(8271x256), split-K=32 ----------------
__global__ void __launch_bounds__(256) k_gemm1(const float* __restrict__ W1)
{
  __shared__ float As[16][64];
  __shared__ float Bs[16][64];
  int mt = blockIdx.x * 64, nt = blockIdx.y * 64, kz = blockIdx.z;
  int kb = kz * KBPER * 16;
  int iters = KBTOT - kz * KBPER;
  if (iters > KBPER) iters = KBPER;
  if (iters < 0) iters = 0;
  int t = threadIdx.x, tx = t & 15, ty = t >> 4;
  float acc[4][4];
  #pragma unroll
  for (int i = 0; i < 4; i++)
    #pragma unroll
    for (int j = 0; j < 4; j++) acc[i][j] = 0.f;
  int am = t & 63, ak = (t >> 6) * 4;
  int bk0 = t >> 4, bn = (t & 15) * 4;

  for (int it = 0; it < iters; it++) {
    int k0 = kb + it * 16;
    float4 av = *(const float4*)&g_feat[(size_t)(mt + am) * FSTRIDE + k0 + ak];
    int gk = k0 + bk0;
    float4 bv = make_float4(0.f, 0.f, 0.f, 0.f);
    if (gk < 8271) bv = *(const float4*)&W1[(size_t)gk * 256 + nt + bn];
    __syncthreads();
    As[ak + 0][am] = av.x; As[ak + 1][am] = av.y;
    As[ak + 2][am] = av.z; As[ak + 3][am] = av.w;
    *(float4*)&Bs[bk0][bn] = bv;
    __syncthreads();
    #pragma unroll
    for (int kk = 0; kk < 16; kk++) {
      float4 a  = *(const float4*)&As[kk][ty * 4];
      float4 bq = *(const float4*)&Bs[kk][tx * 4];
      float ar[4] = {a.x, a.y, a.z, a.w};
      float br[4] = {bq.x, bq.y, bq.z, bq.w};
      #pragma unroll
      for (int i = 0; i < 4; i++)
        #pragma unroll
        for (int j = 0; j < 4; j++)
          acc[i][j] = fmaf(ar[i], br[j], acc[i][j]);
    }
  }
  float* op = &g_gpart[(size_t)kz * (NODES * H1)];
  #pragma unroll
  for (int i = 0; i < 4; i++) {
    float4 vv = make_float4(acc[i][0], acc[i][1], acc[i][2], acc[i][3]);
    *(float4*)&op[(size_t)(mt + ty * 4 + i) * 256 + nt + tx * 4] = vv;
  }
}

// ---------------- K_bt: split-K reduce + bias + relu + MLP tail + combine ----------------
__global__ void __launch_bounds__(256) k_bt(const float* __restrict__ b1,
                                            const float* __restrict__ W2, const float* __restrict__ b2,
                                            const float* __restrict__ W3, const float* __restrict__ b3,
                                            const float* __restrict__ W4, const float* __restrict__ b4,
                                            float* __restrict__ out)
{
  __shared__ float h1s[256], h2s[128], h3s[64], lg[5];
  int node = blockIdx.x, tid = threadIdx.x;
  { float a = b1[tid];
    #pragma unroll
    for (int kz = 0; kz < KSPLIT; kz++)
      a += g_gpart[(size_t)kz * (NODES * H1) + node * 256 + tid];
    h1s[tid] = fmaxf(a, 0.f); }
  __syncthreads();
  if (tid < 128) {
    float a = b2[tid];
    #pragma unroll 8
    for (int k = 0; k < 256; k++) a = fmaf(h1s[k], W2[k * 128 + tid], a);
    h2s[tid] = fmaxf(a, 0.f);
  }
  __syncthreads();
  if (tid < 64) {
    float a = b3[tid];
    #pragma unroll 8
    for (int k = 0; k < 128; k++) a = fmaf(h2s[k], W3[k * 64 + tid], a);
    h3s[tid] = fmaxf(a, 0.f);
  }
  __syncthreads();
  if (tid < 5) {
    float a = b4[tid];
    #pragma unroll 8
    for (int k = 0; k < 64; k++) a = fmaf(h3s[k], W4[k * 5 + tid], a);
    lg[tid] = a;
  }
  __syncthreads();
  if (tid == 0) {
    float hs = 0.f, s12 = 0.f, s23 = 0.f;
    #pragma unroll
    for (int sp = 0; sp < 8; sp++) {
      const float* q = &g_np[(node * 8 + sp) * 3];
      hs += q[0]; s12 += q[1]; s23 += q[2];
    }
    float h_score = hs / 8192.0f;
    float kl1 = logf(0.05f / 0.1f)
              + (0.1f * 0.1f + s12 / 8192.0f) / (2.0f * (0.05f * 0.05f)) - 0.5f;
    float kl2 = logf(0.02f / 0.05f)
              + (0.05f * 0.05f + s23 / 8192.0f) / (2.0f * (0.02f * 0.02f)) - 0.5f;
    float comps[5] = { h_score, -logf(1e-8f), kl1 + kl2, g_htemp[0], g_spec[node] };
    float mxv = lg[0];
    #pragma unroll
    for (int i = 1; i < 5; i++) mxv = fmaxf(mxv, lg[i]);
    float e[5], se = 0.f;
    #pragma unroll
    for (int i = 0; i < 5; i++) { e[i] = expf(lg[i] - mxv); se += e[i]; }
    float o = 0.f;
    #pragma unroll
    for (int i = 0; i < 5; i++) o += (e[i] / se) * comps[i];
    out[node] = o;
  }
}

// ---------------- host: threefry for the 4 subkeys of key(42) ----------------
static void tf20_host(unsigned k0, unsigned k1, unsigned x0, unsigned x1,
                      unsigned* o0, unsigned* o1)
{
  unsigned ks2 = k0 ^ k1 ^ 0x1BD11BDAu;
  unsigned a = x0 + k0, b = x1 + k1;
#define RR(r) { a += b; b = (b << (r)) | (b >> (32 - (r))); b ^= a; }
  RR(13) RR(15) RR(26) RR(6)   a += k1;  b += ks2 + 1u;
  RR(17) RR(29) RR(16) RR(24)  a += ks2; b += k0  + 2u;
  RR(13) RR(15) RR(26) RR(6)   a += k0;  b += k1  + 3u;
  RR(17) RR(29) RR(16) RR(24)  a += k1;  b += ks2 + 4u;
  RR(13) RR(15) RR(26) RR(6)   a += ks2; b += k0  + 5u;
#undef RR
  *o0 = a; *o1 = b;
}

extern "C" void kernel_launch(void* const* d_in, const int* in_sizes, int n_in,
                              void* d_out, int out_size)
{
  const float* z   = (const float*)d_in[0];
  // d_in[1] = y_obs: unused (h_guid reduces to -log(1e-8))
  const float* eh  = (const float*)d_in[2];
  const float* W1  = (const float*)d_in[3];
  const float* b1  = (const float*)d_in[4];
  const float* W2  = (const float*)d_in[5];
  const float* b2  = (const float*)d_in[6];
  const float* W3  = (const float*)d_in[7];
  const float* b3  = (const float*)d_in[8];
  const float* W4  = (const float*)d_in[9];
  const float* b4  = (const float*)d_in[10];
  const int* t_idx = (const int*)d_in[11];
  const int* f_idx = (const int*)d_in[12];
  const int* kptr  = (const int*)d_in[13];
  float* out = (float*)d_out;

  TFK K;
  unsigned s0, s1;
  tf20_host(0u, 42u, 0u, 0u, &s0, &s1); K.a0 = s0; K.a1 = s1; K.a2 = s0 ^ s1 ^ 0x1BD11BDAu;
  tf20_host(0u, 42u, 0u, 1u, &s0, &s1); K.b0 = s0; K.b1 = s1; K.b2 = s0 ^ s1 ^ 0x1BD11BDAu;
  tf20_host(0u, 42u, 0u, 2u, &s0, &s1); K.c0 = s0; K.c1 = s1; K.c2 = s0 ^ s1 ^ 0x1BD11BDAu;
  tf20_host(0u, 42u, 0u, 3u, &s0, &s1); K.d0 = s0; K.d1 = s1; K.d2 = s0 ^ s1 ^ 0x1BD11BDAu;

  k_pre  <<<4609, 256>>>(z, eh, kptr, t_idx, f_idx, K);
  k_gemm1<<<dim3(8, 4, KSPLIT), 256>>>(W1);
  k_bt   <<<NODES, 256>>>(b1, W2, b2, W3, b3, W4, b4, out);
}

// round 11
// speedup vs baseline: 1.0781x; 1.0489x over previous
#include <cuda_runtime.h>
#include <cstdint>

// ---------------- problem constants ----------------
#define NODES   512
#define FSTRIDE 8288           // 8271 features + 17 zero pad (multiple of 16)
#define H1      256
#define KSPLIT  32
#define KBTOT   518            // FSTRIDE/16 k-blocks
#define KBPER   17             // ceil(518/32)

// ---------------- device scratch (static, no allocation) ----------------
__device__ float g_feat[NODES * FSTRIDE];          // ~17 MB feature matrix (zero-padded)
__device__ float g_np[NODES * 8 * 3];              // per (node,split): hs_sum, sum d12^2, sum d23^2
__device__ float g_spec[NODES];                    // spectral entropy per node
__device__ float g_gpart[KSPLIT * NODES * H1];     // split-K GEMM partials (16.8 MB)
__device__ float g_htemp[1];                       // h_temporal

__device__ __constant__ float c_cos16[16] = {
  1.0f, 0.9238795325112867f, 0.7071067811865476f, 0.3826834323650898f,
  0.0f,-0.3826834323650898f,-0.7071067811865476f,-0.9238795325112867f,
 -1.0f,-0.9238795325112867f,-0.7071067811865476f,-0.3826834323650898f,
  0.0f, 0.3826834323650898f, 0.7071067811865476f, 0.9238795325112867f };
__device__ __constant__ float c_sin16[16] = {
  0.0f, 0.3826834323650898f, 0.7071067811865476f, 0.9238795325112867f,
  1.0f, 0.9238795325112867f, 0.7071067811865476f, 0.3826834323650898f,
  0.0f,-0.3826834323650898f,-0.7071067811865476f,-0.9238795325112867f,
 -1.0f,-0.9238795325112867f,-0.7071067811865476f,-0.3826834323650898f };

// ---------------- threefry-2x32-20 (JAX schedule), partitionable draw ----------------
// K.one == 1 at runtime, opaque to ptxas: forces integer adds onto IMAD (fma pipe)
// to balance against the SHF/LOP3 load on the alu pipe.
struct TFK { unsigned a0,a1,a2, b0,b1,b2, c0,c1,c2, d0,d1,d2, one; };

__device__ __forceinline__ unsigned madu(unsigned a, unsigned one, unsigned b)
{
  unsigned d;
  asm("mad.lo.u32 %0, %1, %2, %3;" : "=r"(d) : "r"(a), "r"(one), "r"(b));
  return d;   // a*1 + b == a + b, but issues as IMAD on the fma pipe
}

__device__ __forceinline__ unsigned tfb(unsigned k0, unsigned k1, unsigned ks2,
                                        unsigned idx, unsigned one)
{
  unsigned x0 = k0;               // x0_in = 0 (hi word of iota) + k0
  unsigned x1 = madu(idx, one, k1);
#define TFR(r) { x0 = madu(x0, one, x1); x1 = __funnelshift_l(x1, x1, (r)); x1 ^= x0; }
  TFR(13) TFR(15) TFR(26) TFR(6)
  x0 = madu(x0, one, k1);  x1 = madu(x1, one, ks2 + 1u);
  TFR(17) TFR(29) TFR(16) TFR(24)
  x0 = madu(x0, one, ks2); x1 = madu(x1, one, k0 + 2u);
  TFR(13) TFR(15) TFR(26) TFR(6)
  x0 = madu(x0, one, k0);  x1 = madu(x1, one, k1 + 3u);
  TFR(17) TFR(29) TFR(16) TFR(24)
  x0 = madu(x0, one, k1);  x1 = madu(x1, one, ks2 + 4u);
  TFR(13) TFR(15) TFR(26) TFR(6)
  x0 = madu(x0, one, ks2); x1 = madu(x1, one, k0 + 5u);
#undef TFR
  return x0 ^ x1;  // partitionable 32-bit fold
}

// JAX normal() from raw 32 bits: uniform(-0.99999994, 1) then sqrt(2)*erfinv (XLA/Giles poly)
__device__ __forceinline__ float nrm(unsigned bits)
{
  float u = __uint_as_float((bits >> 9) | 0x3F800000u) - 1.0f;  // [0,1)
  float x = fmaf(u, 2.0f, -0.99999994f);
  x = fmaxf(x, -0.99999994f);
  float w = -__logf(fmaf(x, -x, 1.0f));
  float p;
  if (w < 5.0f) {
    w -= 2.5f;
    p = 2.81022636e-08f;
    p = fmaf(p, w, 3.43273939e-07f);
    p = fmaf(p, w, -3.5233877e-06f);
    p = fmaf(p, w, -4.39150654e-06f);
    p = fmaf(p, w, 0.00021858087f);
    p = fmaf(p, w, -0.00125372503f);
    p = fmaf(p, w, -0.00417768164f);
    p = fmaf(p, w, 0.246640727f);
    p = fmaf(p, w, 1.50140941f);
  } else {
    w = sqrtf(w) - 3.0f;
    p = -0.000200214257f;
    p = fmaf(p, w, 0.000100950558f);
    p = fmaf(p, w, 0.00134934322f);
    p = fmaf(p, w, -0.00367342844f);
    p = fmaf(p, w, 0.00573950773f);
    p = fmaf(p, w, -0.0076224613f);
    p = fmaf(p, w, 0.00943887047f);
    p = fmaf(p, w, 1.00167406f);
    p = fmaf(p, w, 2.83297682f);
  }
  return 1.41421356f * (p * x);
}

// ---------------- block reductions (256 threads) ----------------
__device__ __forceinline__ float bsum256(float v, float* red)
{
  #pragma unroll
  for (int o = 16; o; o >>= 1) v += __shfl_down_sync(0xffffffffu, v, o);
  if ((threadIdx.x & 31) == 0) red[threadIdx.x >> 5] = v;
  __syncthreads();
  if (threadIdx.x == 0) { float r = red[0];
    #pragma unroll
    for (int i = 1; i < 8; i++) r += red[i];
    red[0] = r; }
  __syncthreads();
  float r = red[0];
  __syncthreads();
  return r;
}
__device__ __forceinline__ float bmin256(float v, float* red)
{
  #pragma unroll
  for (int o = 16; o; o >>= 1) v = fminf(v, __shfl_down_sync(0xffffffffu, v, o));
  if ((threadIdx.x & 31) == 0) red[threadIdx.x >> 5] = v;
  __syncthreads();
  if (threadIdx.x == 0) { float r = red[0];
    #pragma unroll
    for (int i = 1; i < 8; i++) r = fminf(r, red[i]);
    red[0] = r; }
  __syncthreads();
  float r = red[0];
  __syncthreads();
  return r;
}
__device__ __forceinline__ float bmax256(float v, float* red)
{
  #pragma unroll
  for (int o = 16; o; o >>= 1) v = fmaxf(v, __shfl_down_sync(0xffffffffu, v, o));
  if ((threadIdx.x & 31) == 0) red[threadIdx.x >> 5] = v;
  __syncthreads();
  if (threadIdx.x == 0) { float r = red[0];
    #pragma unroll
    for (int i = 1; i < 8; i++) r = fmaxf(r, red[i]);
    red[0] = r; }
  __syncthreads();
  float r = red[0];
  __syncthreads();
  return r;
}

// ---------------- K_pre: heterogeneous blocks ----------------
// blocks [0, 4096):    RNG entropies (node = bid>>3, split = bid&7)  -- long pole
// blocks [4096, 4608): per-node stats/median/spectral/feature assembly
// block  4608:         h_temporal
__global__ void __launch_bounds__(256) k_pre(const float* __restrict__ z,
                                             const float* __restrict__ eh,
                                             const int* __restrict__ kptr,
                                             const int* __restrict__ ti,
                                             const int* __restrict__ fi, TFK K)
{
  __shared__ float sz[8192];
  __shared__ float red[8];
  int bid = blockIdx.x;
  int tid = threadIdx.x;

  if (bid < 4096) {
    // ----- RNG path: pure compute, no memory traffic -----
    int node = bid >> 3, split = bid & 7;
    unsigned one = K.one;
    float hs = 0.f, s12 = 0.f, s23 = 0.f;
    #pragma unroll 1
    for (int q = 0; q < 4; q++) {
      int p = split * 1024 + q * 256 + tid;
      // h_score: var over 10 MC samples of (zl + 0.1 n); zl cancels in the variance
      unsigned mb = (unsigned)node * 81920u + (unsigned)p;
      float s1 = 0.f, s2 = 0.f;
      #pragma unroll
      for (int s = 0; s < 10; s++) {
        float n = nrm(tfb(K.a0, K.a1, K.a2, mb + (unsigned)s * 8192u, one));
        s1 += n;
        s2 = fmaf(n, n, s2);
      }
      float v = 0.01f * ((s2 - s1 * s1 * 0.1f) * (1.0f / 9.0f));
      hs += 0.5f * __logf(17.07946844534713f * (v + 1e-8f));  // fast log: |err| ~1e-7 abs
      // h_solver: (e1-e2)^2 and (e2-e3)^2 sums (zl cancels in the differences)
      unsigned pb = (unsigned)node * 8192u + (unsigned)p;
      float nb = nrm(tfb(K.b0, K.b1, K.b2, pb, one));
      float nc = nrm(tfb(K.c0, K.c1, K.c2, pb, one));
      float nd = nrm(tfb(K.d0, K.d1, K.d2, pb, one));
      float d1 = 0.1f  * nb - 0.05f * nc;
      float d2 = 0.05f * nc - 0.02f * nd;
      s12 = fmaf(d1, d1, s12);
      s23 = fmaf(d2, d2, s23);
    }
    hs  = bsum256(hs, red);
    s12 = bsum256(s12, red);
    s23 = bsum256(s23, red);
    if (tid == 0) {
      float* o = &g_np[(node * 8 + split) * 3];
      o[0] = hs; o[1] = s12; o[2] = s23;
    }
    return;
  }

  if (bid == 4608) {
    // ----- h_temporal -----
    float s = 0.f;
    for (int i = tid; i < 1536; i += 256) s += eh[i + 512] - eh[i];
    float tot = bsum256(s, red);
    float mean = tot / 1536.0f;
    float v = 0.f;
    for (int i = tid; i < 1536; i += 256) {
      float d = (eh[i + 512] - eh[i]) - mean;
      v = fmaf(d, d, v);
    }
    float VAR = bsum256(v, red) / 1535.0f;
    if (tid == 0)
      g_htemp[0] = 0.5f * logf(17.07946844534713f * (VAR + 1e-6f));
    return;
  }

  // ----- per-node path -----
  int node = bid - 4096;
  int t = ti[node], f = fi[node];
  float* fb = &g_feat[(size_t)node * FSTRIDE];

  for (int p = tid; p < 8192; p += 256) {
    int b = p >> 8, i = (p >> 4) & 15, j = p & 15;
    float v = z[((size_t)(b * 4096 + t * 16 + i)) * 512 + f * 16 + j];
    sz[p] = v;
    fb[p] = v;
  }
  __syncthreads();

  // stats pass 1
  float s = 0.f, sa = 0.f, sq = 0.f, cp = 0.f, cn = 0.f, mn = 3e38f, mx = -3e38f;
  for (int p = tid; p < 8192; p += 256) {
    float v = sz[p];
    s += v; sa += fabsf(v); sq = fmaf(v, v, sq);
    if (v > 0.f) cp += 1.f;
    if (v < 0.f) cn += 1.f;
    mn = fminf(mn, v); mx = fmaxf(mx, v);
  }
  float S  = bsum256(s,  red);
  float SA = bsum256(sa, red);
  float SQ = bsum256(sq, red);
  float CP = bsum256(cp, red);
  float CN = bsum256(cn, red);
  float MN = bmin256(mn, red);
  float MX = bmax256(mx, red);
  float mean = S / 8192.0f;

  float cv = 0.f;
  for (int p = tid; p < 8192; p += 256) { float d = sz[p] - mean; cv = fmaf(d, d, cv); }
  float VAR = bsum256(cv, red) / 8191.0f;

  // exact median (rank 4095) via bit bisection on order-mapped keys
  unsigned lo = 0u, hi = 0xFFFFFFFFu;
  #pragma unroll 1
  for (int it = 0; it < 32 && lo < hi; it++) {
    unsigned mid = lo + ((hi - lo) >> 1);
    float c = 0.f;
    for (int p = tid; p < 8192; p += 256) {
      unsigned u = __float_as_uint(sz[p]);
      unsigned kk = (u & 0x80000000u) ? ~u : (u | 0x80000000u);
      if (kk <= mid) c += 1.f;
    }
    float C = bsum256(c, red);
    if (C >= 4096.f) hi = mid; else lo = mid + 1u;
  }
  float med;
  { unsigned kk = lo;
    unsigned u = (kk >> 31) ? (kk ^ 0x80000000u) : ~kk;
    med = __uint_as_float(u); }

  // spectral entropy: 16-pt DFT along local time axis, per (b, col)
  float hsp = 0.f;
  for (int c = tid; c < 512; c += 256) {
    int b = c >> 4, j = c & 15;
    float xr[16];
    #pragma unroll
    for (int i2 = 0; i2 < 16; i2++) xr[i2] = sz[b * 256 + i2 * 16 + j];
    float ps[9];
    #pragma unroll
    for (int k2 = 0; k2 < 9; k2++) {
      float re = 0.f, im = 0.f;
      #pragma unroll
      for (int i2 = 0; i2 < 16; i2++) {
        int w = (k2 * i2) & 15;
        re = fmaf(xr[i2], c_cos16[w], re);
        im = fmaf(xr[i2], c_sin16[w], im);
      }
      ps[k2] = fmaf(re, re, im * im);
    }
    float den = ps[0] + ps[8];
    #pragma unroll
    for (int k2 = 1; k2 < 8; k2++) den += 2.0f * ps[k2];
    float dent = den + 1e-8f;
    #pragma unroll
    for (int k2 = 0; k2 < 9; k2++) {
      float pn = ps[k2] / dent;
      float tm = pn * logf(pn + 1e-8f);
      hsp += (k2 == 0 || k2 == 8) ? tm : 2.0f * tm;
    }
  }
  float HS = bsum256(hsp, red);
  if (tid == 0) g_spec[node] = -HS;

  // feature tail: k_embed computed per-block (no cross-block dependency)
  if (tid < 32) {
    float kf = (float)(*kptr);
    float val = kf * expf((float)tid * -0.29710775393471563f);  // -ln(10000)/31
    fb[8192 + tid] = sinf(val);
    fb[8224 + tid] = cosf(val);
  }
  if (tid == 64) {
    float tf = (float)t, ff = (float)f;
    fb[8256] = sinf(0.1f * tf); fb[8257] = cosf(0.1f * tf);
    fb[8258] = sinf(0.1f * ff); fb[8259] = cosf(0.1f * ff);
    fb[8260] = 0.5f;   // S_SCALE / MAX_SCALES
  }
  if (tid == 0) {
    fb[8261] = mean;
    fb[8262] = sqrtf(VAR);
    fb[8263] = MN;
    fb[8264] = MX;
    fb[8265] = med;
    fb[8266] = VAR;
    fb[8267] = sqrtf(SQ);
    fb[8268] = SA;
    fb[8269] = CP;
    fb[8270] = CN;
  }
  if (tid >= 96 && tid < 96 + 17) fb[8271 - 96 + tid] = 0.f;  // zero pad [8271, 8288)
}

// ---------------- GEMM1: feat(512x8288) @ W1(8271x256), split-K=32 ----------------
__global__ void __launch_bounds__(256) k_gemm1(const float* __restrict__ W1)
{
  __shared__ float As[16][64];
  __shared__ float Bs[16][64];
  int mt = blockIdx.x * 64, nt = blockIdx.y * 64, kz = blockIdx.z;
  int kb = kz * KBPER * 16;
  int iters = KBTOT - kz * KBPER;
  if (iters > KBPER) iters = KBPER;
  if (iters < 0) iters = 0;
  int t = threadIdx.x, tx = t & 15, ty = t >> 4;
  float acc[4][4];
  #pragma unroll
  for (int i = 0; i < 4; i++)
    #pragma unroll
    for (int j = 0; j < 4; j++) acc[i][j] = 0.f;
  int am = t & 63, ak = (t >> 6) * 4;
  int bk0 = t >> 4, bn = (t & 15) * 4;

  for (int it = 0; it < iters; it++) {
    int k0 = kb + it * 16;
    float4 av = *(const float4*)&g_feat[(size_t)(mt + am) * FSTRIDE + k0 + ak];
    int gk = k0 + bk0;
    float4 bv = make_float4(0.f, 0.f, 0.f, 0.f);
    if (gk < 8271) bv = *(const float4*)&W1[(size_t)gk * 256 + nt + bn];
    __syncthreads();
    As[ak + 0][am] = av.x; As[ak + 1][am] = av.y;
    As[ak + 2][am] = av.z; As[ak + 3][am] = av.w;
    *(float4*)&Bs[bk0][bn] = bv;
    __syncthreads();
    #pragma unroll
    for (int kk = 0; kk < 16; kk++) {
      float4 a  = *(const float4*)&As[kk][ty * 4];
      float4 bq = *(const float4*)&Bs[kk][tx * 4];
      float ar[4] = {a.x, a.y, a.z, a.w};
      float br[4] = {bq.x, bq.y, bq.z, bq.w};
      #pragma unroll
      for (int i = 0; i < 4; i++)
        #pragma unroll
        for (int j = 0; j < 4; j++)
          acc[i][j] = fmaf(ar[i], br[j], acc[i][j]);
    }
  }
  float* op = &g_gpart[(size_t)kz * (NODES * H1)];
  #pragma unroll
  for (int i = 0; i < 4; i++) {
    float4 vv = make_float4(acc[i][0], acc[i][1], acc[i][2], acc[i][3]);
    *(float4*)&op[(size_t)(mt + ty * 4 + i) * 256 + nt + tx * 4] = vv;
  }
}

// ---------------- K_bt: split-K reduce + bias + relu + MLP tail + combine ----------------
__global__ void __launch_bounds__(256) k_bt(const float* __restrict__ b1,
                                            const float* __restrict__ W2, const float* __restrict__ b2,
                                            const float* __restrict__ W3, const float* __restrict__ b3,
                                            const float* __restrict__ W4, const float* __restrict__ b4,
                                            float* __restrict__ out)
{
  __shared__ float h1s[256], h2s[128], h3s[64], lg[5];
  int node = blockIdx.x, tid = threadIdx.x;
  { float a = b1[tid];
    #pragma unroll
    for (int kz = 0; kz < KSPLIT; kz++)
      a += g_gpart[(size_t)kz * (NODES * H1) + node * 256 + tid];
    h1s[tid] = fmaxf(a, 0.f); }
  __syncthreads();
  if (tid < 128) {
    float a = b2[tid];
    #pragma unroll 8
    for (int k = 0; k < 256; k++) a = fmaf(h1s[k], W2[k * 128 + tid], a);
    h2s[tid] = fmaxf(a, 0.f);
  }
  __syncthreads();
  if (tid < 64) {
    float a = b3[tid];
    #pragma unroll 8
    for (int k = 0; k < 128; k++) a = fmaf(h2s[k], W3[k * 64 + tid], a);
    h3s[tid] = fmaxf(a, 0.f);
  }
  __syncthreads();
  if (tid < 5) {
    float a = b4[tid];
    #pragma unroll 8
    for (int k = 0; k < 64; k++) a = fmaf(h3s[k], W4[k * 5 + tid], a);
    lg[tid] = a;
  }
  __syncthreads();
  if (tid == 0) {
    float hs = 0.f, s12 = 0.f, s23 = 0.f;
    #pragma unroll
    for (int sp = 0; sp < 8; sp++) {
      const float* q = &g_np[(node * 8 + sp) * 3];
      hs += q[0]; s12 += q[1]; s23 += q[2];
    }
    float h_score = hs / 8192.0f;
    float kl1 = logf(0.05f / 0.1f)
              + (0.1f * 0.1f + s12 / 8192.0f) / (2.0f * (0.05f * 0.05f)) - 0.5f;
    float kl2 = logf(0.02f / 0.05f)
              + (0.05f * 0.05f + s23 / 8192.0f) / (2.0f * (0.02f * 0.02f)) - 0.5f;
    float comps[5] = { h_score, -logf(1e-8f), kl1 + kl2, g_htemp[0], g_spec[node] };
    float mxv = lg[0];
    #pragma unroll
    for (int i = 1; i < 5; i++) mxv = fmaxf(mxv, lg[i]);
    float e[5], se = 0.f;
    #pragma unroll
    for (int i = 0; i < 5; i++) { e[i] = expf(lg[i] - mxv); se += e[i]; }
    float o = 0.f;
    #pragma unroll
    for (int i = 0; i < 5; i++) o += (e[i] / se) * comps[i];
    out[node] = o;
  }
}

// ---------------- host: threefry for the 4 subkeys of key(42) ----------------
static void tf20_host(unsigned k0, unsigned k1, unsigned x0, unsigned x1,
                      unsigned* o0, unsigned* o1)
{
  unsigned ks2 = k0 ^ k1 ^ 0x1BD11BDAu;
  unsigned a = x0 + k0, b = x1 + k1;
#define RR(r) { a += b; b = (b << (r)) | (b >> (32 - (r))); b ^= a; }
  RR(13) RR(15) RR(26) RR(6)   a += k1;  b += ks2 + 1u;
  RR(17) RR(29) RR(16) RR(24)  a += ks2; b += k0  + 2u;
  RR(13) RR(15) RR(26) RR(6)   a += k0;  b += k1  + 3u;
  RR(17) RR(29) RR(16) RR(24)  a += k1;  b += ks2 + 4u;
  RR(13) RR(15) RR(26) RR(6)   a += ks2; b += k0  + 5u;
#undef RR
  *o0 = a; *o1 = b;
}

extern "C" void kernel_launch(void* const* d_in, const int* in_sizes, int n_in,
                              void* d_out, int out_size)
{
  const float* z   = (const float*)d_in[0];
  // d_in[1] = y_obs: unused (h_guid reduces to -log(1e-8))
  const float* eh  = (const float*)d_in[2];
  const float* W1  = (const float*)d_in[3];
  const float* b1  = (const float*)d_in[4];
  const float* W2  = (const float*)d_in[5];
  const float* b2  = (const float*)d_in[6];
  const float* W3  = (const float*)d_in[7];
  const float* b3  = (const float*)d_in[8];
  const float* W4  = (const float*)d_in[9];
  const float* b4  = (const float*)d_in[10];
  const int* t_idx = (const int*)d_in[11];
  const int* f_idx = (const int*)d_in[12];
  const int* kptr  = (const int*)d_in[13];
  float* out = (float*)d_out;

  TFK K;
  unsigned s0, s1;
  tf20_host(0u, 42u, 0u, 0u, &s0, &s1); K.a0 = s0; K.a1 = s1; K.a2 = s0 ^ s1 ^ 0x1BD11BDAu;
  tf20_host(0u, 42u, 0u, 1u, &s0, &s1); K.b0 = s0; K.b1 = s1; K.b2 = s0 ^ s1 ^ 0x1BD11BDAu;
  tf20_host(0u, 42u, 0u, 2u, &s0, &s1); K.c0 = s0; K.c1 = s1; K.c2 = s0 ^ s1 ^ 0x1BD11BDAu;
  tf20_host(0u, 42u, 0u, 3u, &s0, &s1); K.d0 = s0; K.d1 = s1; K.d2 = s0 ^ s1 ^ 0x1BD11BDAu;
  K.one = 1u;

  k_pre  <<<4609, 256>>>(z, eh, kptr, t_idx, f_idx, K);
  k_gemm1<<<dim3(8, 4, KSPLIT), 256>>>(W1);
  k_bt   <<<NODES, 256>>>(b1, W2, b2, W3, b3, W4, b4, out);
}